// round 6
// baseline (speedup 1.0000x reference)
#include <cuda_runtime.h>

#define NSEG 2048
#define EPS 1e-6f
#define THREADS 1024
#define NWARPS (THREADS / 32)

__device__ __forceinline__ float warp_sum(float x) {
#pragma unroll
    for (int o = 16; o > 0; o >>= 1) x += __shfl_xor_sync(0xFFFFFFFFu, x, o);
    return x;
}

__device__ __forceinline__ int lower_bound(const int* __restrict__ batch, int n, int key) {
    int lo = 0, hi = n;
    while (lo < hi) {
        int mid = (lo + hi) >> 1;
        if (__ldg(&batch[mid]) < key) lo = mid + 1; else hi = mid;
    }
    return lo;
}

// One CTA per segment, 1024 threads, 2 CTAs/SM. NO smem stash: pass-1 fills
// L2 (296 resident CTAs x ~245KB = ~72MB << 126MB L2), pass-2 re-reads hit
// L2. Pure LDG/STG stream keeps the LSU free for maximum MLP (the smem
// stash in R4/R5 cost ~10% achieved DRAM BW). Streaming stores for outputs.
__global__ void __launch_bounds__(THREADS, 2)
fused_seg_kernel(const float4* __restrict__ s4,
                 const float4* __restrict__ v4,
                 const float4* __restrict__ w4,
                 const float4* __restrict__ b4,
                 const int*    __restrict__ batch,
                 int n,
                 float4* __restrict__ outs4,
                 float4* __restrict__ outv4) {
    __shared__ float red[3][NWARPS];
    __shared__ float stats[3];               // m, invvar, invvm
    __shared__ int bounds[2];

    int seg = blockIdx.x;
    int t = threadIdx.x;
    int warp = t >> 5, lane = t & 31;

    if (warp == 0 && lane < 2)
        bounds[lane] = lower_bound(batch, n, seg + lane);
    __syncthreads();

    int start = bounds[0];
    int count = bounds[1] - start;
    if (count == 0) return;

    long long sbase = (long long)start * 64;   // float4 index into s
    long long vbase = (long long)start * 96;   // float4 index into v
    int ns4 = count * 64;
    int nv4 = count * 96;

    // ---- Pass 1: accumulate sums (fills L2 with this segment) ----
    float ss = 0.0f, ss2 = 0.0f, sv2 = 0.0f;
#pragma unroll 4
    for (int i = t; i < ns4; i += THREADS) {
        float4 a = s4[sbase + i];
        ss  += a.x + a.y + a.z + a.w;
        ss2 += a.x * a.x + a.y * a.y + a.z * a.z + a.w * a.w;
    }
#pragma unroll 4
    for (int i = t; i < nv4; i += THREADS) {
        float4 a = v4[vbase + i];
        sv2 += a.x * a.x + a.y * a.y + a.z * a.z + a.w * a.w;
    }

    ss  = warp_sum(ss);
    ss2 = warp_sum(ss2);
    sv2 = warp_sum(sv2);
    if (lane == 0) { red[0][warp] = ss; red[1][warp] = ss2; red[2][warp] = sv2; }
    __syncthreads();
    if (warp == 0) {
        float a0 = (lane < NWARPS) ? red[0][lane] : 0.0f;
        float a1 = (lane < NWARPS) ? red[1][lane] : 0.0f;
        float a2 = (lane < NWARPS) ? red[2][lane] : 0.0f;
        a0 = warp_sum(a0); a1 = warp_sum(a1); a2 = warp_sum(a2);
        if (lane == 0) {
            float cnt = (float)count;
            float denom_s = cnt * 256.0f;
            float m = a0 / denom_s;
            float var = a1 / denom_s - m * m;
            var = fmaxf(var, EPS);
            float vmean = a2 / (cnt * 128.0f);
            vmean = fmaxf(vmean, EPS);
            stats[0] = m;
            stats[1] = 1.0f / var;
            stats[2] = 1.0f / vmean;
        }
    }
    __syncthreads();

    float m   = stats[0];
    float ivr = stats[1];
    float ivm = stats[2];

    // ---- Pass 2 (LIFO): v first (youngest in L2), then s ----
#pragma unroll 4
    for (int i = t; i < nv4; i += THREADS) {
        long long g = vbase + i;
        float4 a = __ldcs(&v4[g]);           // evict-first after consumption
        float4 o;
        o.x = a.x * ivm;
        o.y = a.y * ivm;
        o.z = a.z * ivm;
        o.w = a.w * ivm;
        __stcs(&outv4[g], o);                // don't pollute L2 with outputs
    }
#pragma unroll 4
    for (int i = t; i < ns4; i += THREADS) {
        long long g = sbase + i;
        float4 a = __ldcs(&s4[g]);
        int cg = (int)(g & 63);              // 64 float4 per node row
        float4 w = __ldg(&w4[cg]);
        float4 b = __ldg(&b4[cg]);
        float4 o;
        o.x = (a.x - m) * ivr * w.x + b.x;
        o.y = (a.y - m) * ivr * w.y + b.y;
        o.z = (a.z - m) * ivr * w.z + b.z;
        o.w = (a.w - m) * ivr * w.w + b.w;
        __stcs(&outs4[g], o);
    }
}

extern "C" void kernel_launch(void* const* d_in, const int* in_sizes, int n_in,
                              void* d_out, int out_size) {
    const float* s      = (const float*)d_in[0];
    const float* v      = (const float*)d_in[1];
    const float* weight = (const float*)d_in[2];
    const float* bias   = (const float*)d_in[3];
    const int*   batch  = (const int*)d_in[4];

    int n = in_sizes[4];
    float* out_s = (float*)d_out;
    float* out_v = out_s + (size_t)n * 256;

    fused_seg_kernel<<<NSEG, THREADS>>>(
        (const float4*)s, (const float4*)v,
        (const float4*)weight, (const float4*)bias,
        batch, n,
        (float4*)out_s, (float4*)out_v);
}

// round 7
// speedup vs baseline: 1.0306x; 1.0306x over previous
#include <cuda_runtime.h>

#define NSEG 2048
#define EPS 1e-6f
#define THREADS 1024
#define NWARPS (THREADS / 32)
#define SMEM_F4 6144   // 96KB float4 stash: covers ~98% of a segment's s-data

__device__ __forceinline__ float warp_sum(float x) {
#pragma unroll
    for (int o = 16; o > 0; o >>= 1) x += __shfl_xor_sync(0xFFFFFFFFu, x, o);
    return x;
}

__device__ __forceinline__ float warp_sum2(float& y, float x) {
#pragma unroll
    for (int o = 16; o > 0; o >>= 1) {
        x += __shfl_xor_sync(0xFFFFFFFFu, x, o);
        y += __shfl_xor_sync(0xFFFFFFFFu, y, o);
    }
    return x;
}

__device__ __forceinline__ int lower_bound(const int* __restrict__ batch, int n, int key) {
    int lo = 0, hi = n;
    while (lo < hi) {
        int mid = (lo + hi) >> 1;
        if (__ldg(&batch[mid]) < key) lo = mid + 1; else hi = mid;
    }
    return lo;
}

// One CTA per segment; 3-phase schedule to keep DRAM fed with a mixed
// read+write stream instead of pure-read then pure-write:
//   A: read s -> stash in 96KB smem + accumulate; reduce s-stats.
//   B: read v (accumulate sv2)  THEN  normalize+write s (stash/L2) -- no
//      barrier between, so v-reads and s-writes overlap at the DRAM.
//   C: reduce v-stats; re-read v (L2 hit) and write v.
__global__ void __launch_bounds__(THREADS, 2)
fused_seg_kernel(const float4* __restrict__ s4,
                 const float4* __restrict__ v4,
                 const float4* __restrict__ w4,
                 const float4* __restrict__ b4,
                 const int*    __restrict__ batch,
                 int n,
                 float4* __restrict__ outs4,
                 float4* __restrict__ outv4) {
    extern __shared__ float4 s_stash[];      // SMEM_F4 entries
    __shared__ float red[3][NWARPS];
    __shared__ float stats_s[2];             // m, invvar
    __shared__ float stats_v;                // invvm
    __shared__ int bounds[2];

    int seg = blockIdx.x;
    int t = threadIdx.x;
    int warp = t >> 5, lane = t & 31;

    if (warp == 0 && lane < 2)
        bounds[lane] = lower_bound(batch, n, seg + lane);
    __syncthreads();

    int start = bounds[0];
    int count = bounds[1] - start;
    if (count == 0) return;

    long long sbase = (long long)start * 64;   // float4 index into s
    long long vbase = (long long)start * 96;   // float4 index into v
    int ns4 = count * 64;
    int nv4 = count * 96;
    int stash_n = (ns4 < SMEM_F4) ? ns4 : SMEM_F4;

    // ---- Phase A: read s, stash, accumulate s-sums ----
    float ss = 0.0f, ss2 = 0.0f;
#pragma unroll 2
    for (int i = t; i < ns4; i += THREADS) {
        float4 a = s4[sbase + i];
        if (i < SMEM_F4) s_stash[i] = a;
        ss  += a.x + a.y + a.z + a.w;
        ss2 += a.x * a.x + a.y * a.y + a.z * a.z + a.w * a.w;
    }
    ss = warp_sum2(ss2, ss);
    if (lane == 0) { red[0][warp] = ss; red[1][warp] = ss2; }
    __syncthreads();
    if (warp == 0) {
        float a0 = (lane < NWARPS) ? red[0][lane] : 0.0f;
        float a1 = (lane < NWARPS) ? red[1][lane] : 0.0f;
        a0 = warp_sum2(a1, a0);
        if (lane == 0) {
            float denom_s = (float)count * 256.0f;
            float m = a0 / denom_s;
            float var = a1 / denom_s - m * m;
            var = fmaxf(var, EPS);
            stats_s[0] = m;
            stats_s[1] = 1.0f / var;
        }
    }
    __syncthreads();

    float m   = stats_s[0];
    float ivr = stats_s[1];

    // ---- Phase B: read v (accumulate) + normalize/write s (no barrier
    //      between the two loops: v-loads overlap s-stores at DRAM) ----
    float sv2 = 0.0f;
#pragma unroll 4
    for (int i = t; i < nv4; i += THREADS) {
        float4 a = v4[vbase + i];
        sv2 += a.x * a.x + a.y * a.y + a.z * a.z + a.w * a.w;
    }
#pragma unroll 2
    for (int i = t; i < ns4; i += THREADS) {
        long long g = sbase + i;
        float4 a = (i < stash_n) ? s_stash[i] : __ldcs(&s4[g]);
        int cg = (int)(g & 63);              // 64 float4 per node row
        float4 w = __ldg(&w4[cg]);
        float4 b = __ldg(&b4[cg]);
        float4 o;
        o.x = (a.x - m) * ivr * w.x + b.x;
        o.y = (a.y - m) * ivr * w.y + b.y;
        o.z = (a.z - m) * ivr * w.z + b.z;
        o.w = (a.w - m) * ivr * w.w + b.w;
        __stcs(&outs4[g], o);
    }

    // ---- reduce v-stats ----
    sv2 = warp_sum(sv2);
    if (lane == 0) red[2][warp] = sv2;
    __syncthreads();
    if (warp == 0) {
        float a2 = (lane < NWARPS) ? red[2][lane] : 0.0f;
        a2 = warp_sum(a2);
        if (lane == 0) {
            float vmean = a2 / ((float)count * 128.0f);
            vmean = fmaxf(vmean, EPS);
            stats_v = 1.0f / vmean;
        }
    }
    __syncthreads();

    float ivm = stats_v;

    // ---- Phase C: re-read v (L2 hit), scale, write ----
#pragma unroll 4
    for (int i = t; i < nv4; i += THREADS) {
        long long g = vbase + i;
        float4 a = __ldcs(&v4[g]);
        float4 o;
        o.x = a.x * ivm;
        o.y = a.y * ivm;
        o.z = a.z * ivm;
        o.w = a.w * ivm;
        __stcs(&outv4[g], o);
    }
}

extern "C" void kernel_launch(void* const* d_in, const int* in_sizes, int n_in,
                              void* d_out, int out_size) {
    const float* s      = (const float*)d_in[0];
    const float* v      = (const float*)d_in[1];
    const float* weight = (const float*)d_in[2];
    const float* bias   = (const float*)d_in[3];
    const int*   batch  = (const int*)d_in[4];

    int n = in_sizes[4];
    float* out_s = (float*)d_out;
    float* out_v = out_s + (size_t)n * 256;

    const int SMEM_BYTES = SMEM_F4 * 16;   // 96KB -> 2 CTAs/SM + s stash
    cudaFuncSetAttribute(fused_seg_kernel,
                         cudaFuncAttributeMaxDynamicSharedMemorySize, SMEM_BYTES);

    fused_seg_kernel<<<NSEG, THREADS, SMEM_BYTES>>>(
        (const float4*)s, (const float4*)v,
        (const float4*)weight, (const float4*)bias,
        batch, n,
        (float4*)out_s, (float4*)out_v);
}

// round 8
// speedup vs baseline: 1.0652x; 1.0335x over previous
#include <cuda_runtime.h>

#define NSEG 2048
#define EPS 1e-6f
#define THREADS 1024
#define NWARPS (THREADS / 32)
#define SMEM_F4 6144   // 96KB float4 stash: covers ~98% of a segment's s-data
#define GRID 304       // persistent: 2 CTAs/SM x 152 SMs

__device__ int g_seg_start[NSEG + 1];

__global__ void bounds_kernel(const int* __restrict__ batch, int n) {
    int g = blockIdx.x * blockDim.x + threadIdx.x;
    if (g > NSEG) return;
    int lo = 0, hi = n;
    while (lo < hi) {
        int mid = (lo + hi) >> 1;
        if (__ldg(&batch[mid]) < g) lo = mid + 1; else hi = mid;
    }
    g_seg_start[g] = lo;
}

__device__ __forceinline__ void warp_sum3(float& a, float& b, float& c) {
#pragma unroll
    for (int o = 16; o > 0; o >>= 1) {
        a += __shfl_xor_sync(0xFFFFFFFFu, a, o);
        b += __shfl_xor_sync(0xFFFFFFFFu, b, o);
        c += __shfl_xor_sync(0xFFFFFFFFu, c, o);
    }
}

// Persistent CTAs, one segment per loop iteration, ONE barrier per segment:
//  - pass 1: read s (stash in 96KB smem) + v, accumulate 3 sums
//  - warps dump partials into parity-double-buffered red[][], __syncthreads
//  - every warp redundantly reduces partials (3 LDS + shuffles) and computes
//    stats per-thread (no second barrier, no single-warp serialization)
//  - pass 2: v from L2, s from smem stash (each thread re-reads only the
//    stash slots it wrote -> no barrier needed), streaming stores.
__global__ void __launch_bounds__(THREADS, 2)
fused_seg_kernel(const float4* __restrict__ s4,
                 const float4* __restrict__ v4,
                 const float4* __restrict__ w4,
                 const float4* __restrict__ b4,
                 float4* __restrict__ outs4,
                 float4* __restrict__ outv4) {
    extern __shared__ float4 s_stash[];          // SMEM_F4 entries
    __shared__ float red[2][3][NWARPS];          // parity double buffer

    int t = threadIdx.x;
    int warp = t >> 5, lane = t & 31;
    int parity = 0;

    for (int seg = blockIdx.x; seg < NSEG; seg += gridDim.x) {
        int start = __ldg(&g_seg_start[seg]);
        int count = __ldg(&g_seg_start[seg + 1]) - start;
        if (count == 0) continue;

        long long sbase = (long long)start * 64;   // float4 index into s
        long long vbase = (long long)start * 96;   // float4 index into v
        int ns4 = count * 64;
        int nv4 = count * 96;
        int stash_n = (ns4 < SMEM_F4) ? ns4 : SMEM_F4;

        // ---- Pass 1: read s (stash) + v, accumulate ----
        float ss = 0.0f, ss2 = 0.0f, sv2 = 0.0f;
#pragma unroll 2
        for (int i = t; i < ns4; i += THREADS) {
            float4 a = s4[sbase + i];
            if (i < SMEM_F4) s_stash[i] = a;
            ss  += a.x + a.y + a.z + a.w;
            ss2 += a.x * a.x + a.y * a.y + a.z * a.z + a.w * a.w;
        }
#pragma unroll 4
        for (int i = t; i < nv4; i += THREADS) {
            float4 a = v4[vbase + i];
            sv2 += a.x * a.x + a.y * a.y + a.z * a.z + a.w * a.w;
        }

        warp_sum3(ss, ss2, sv2);
        if (lane == 0) {
            red[parity][0][warp] = ss;
            red[parity][1][warp] = ss2;
            red[parity][2][warp] = sv2;
        }
        __syncthreads();   // the ONLY barrier per segment

        // Redundant cross-warp reduce in every warp (lane i holds warp i's
        // partial; conflict-free 128B LDS rows, then shuffle tree).
        float a0 = red[parity][0][lane];
        float a1 = red[parity][1][lane];
        float a2 = red[parity][2][lane];
        warp_sum3(a0, a1, a2);
        parity ^= 1;

        float cnt = (float)count;
        float denom_s = cnt * 256.0f;
        float m = a0 / denom_s;
        float var = fmaxf(a1 / denom_s - m * m, EPS);
        float ivr = 1.0f / var;
        float ivm = 1.0f / fmaxf(a2 / (cnt * 128.0f), EPS);

        // ---- Pass 2 (LIFO): v first (L2 hit), then s (smem stash) ----
#pragma unroll 4
        for (int i = t; i < nv4; i += THREADS) {
            long long g = vbase + i;
            float4 a = __ldcs(&v4[g]);
            float4 o;
            o.x = a.x * ivm;
            o.y = a.y * ivm;
            o.z = a.z * ivm;
            o.w = a.w * ivm;
            __stcs(&outv4[g], o);
        }
#pragma unroll 2
        for (int i = t; i < ns4; i += THREADS) {
            long long g = sbase + i;
            float4 a = (i < stash_n) ? s_stash[i] : __ldcs(&s4[g]);
            int cg = i & 63;                 // 64 float4 per node row
            float4 w = __ldg(&w4[cg]);
            float4 b = __ldg(&b4[cg]);
            float4 o;
            o.x = (a.x - m) * ivr * w.x + b.x;
            o.y = (a.y - m) * ivr * w.y + b.y;
            o.z = (a.z - m) * ivr * w.z + b.z;
            o.w = (a.w - m) * ivr * w.w + b.w;
            __stcs(&outs4[g], o);
        }
    }
}

extern "C" void kernel_launch(void* const* d_in, const int* in_sizes, int n_in,
                              void* d_out, int out_size) {
    const float* s      = (const float*)d_in[0];
    const float* v      = (const float*)d_in[1];
    const float* weight = (const float*)d_in[2];
    const float* bias   = (const float*)d_in[3];
    const int*   batch  = (const int*)d_in[4];

    int n = in_sizes[4];
    float* out_s = (float*)d_out;
    float* out_v = out_s + (size_t)n * 256;

    bounds_kernel<<<(NSEG + 1 + 255) / 256, 256>>>(batch, n);

    const int SMEM_BYTES = SMEM_F4 * 16;   // 96KB -> 2 CTAs/SM + s stash
    cudaFuncSetAttribute(fused_seg_kernel,
                         cudaFuncAttributeMaxDynamicSharedMemorySize, SMEM_BYTES);

    fused_seg_kernel<<<GRID, THREADS, SMEM_BYTES>>>(
        (const float4*)s, (const float4*)v,
        (const float4*)weight, (const float4*)bias,
        (float4*)out_s, (float4*)out_v);
}

// round 9
// speedup vs baseline: 1.1023x; 1.0349x over previous
#include <cuda_runtime.h>

#define NSEG 2048
#define EPS 1e-6f
#define THREADS 1024
#define NWARPS (THREADS / 32)
#define SMEM_F4 6144   // 96KB float4 stash: covers ~98% of a segment's s-data
#define GRID 304       // persistent: 2 CTAs/SM x 152 SMs

__device__ int g_seg_start[NSEG + 1];

// Linear boundary scan: coalesced read of batch[], write seg starts only at
// discontinuities. No dependent-load chains (unlike binary search).
__global__ void bounds_scan_kernel(const int* __restrict__ batch, int n) {
    int i = blockIdx.x * blockDim.x + threadIdx.x;
    if (i >= n) return;
    int b1 = batch[i];
    if (i == 0) {
        for (int g = 0; g <= b1; g++) g_seg_start[g] = 0;
    } else {
        int b0 = batch[i - 1];
        for (int g = b0 + 1; g <= b1; g++) g_seg_start[g] = i;
    }
    if (i == n - 1) {
        for (int g = b1 + 1; g <= NSEG; g++) g_seg_start[g] = n;
    }
}

__device__ __forceinline__ void warp_sum3(float& a, float& b, float& c) {
#pragma unroll
    for (int o = 16; o > 0; o >>= 1) {
        a += __shfl_xor_sync(0xFFFFFFFFu, a, o);
        b += __shfl_xor_sync(0xFFFFFFFFu, b, o);
        c += __shfl_xor_sync(0xFFFFFFFFu, c, o);
    }
}

// Persistent CTAs, one segment per loop iteration, ONE barrier per segment.
// (see R8: parity-double-buffered reduction, redundant per-warp final
// reduce, s re-read from private smem stash, v re-read from L2, streaming
// stores.)
__global__ void __launch_bounds__(THREADS, 2)
fused_seg_kernel(const float4* __restrict__ s4,
                 const float4* __restrict__ v4,
                 const float4* __restrict__ w4,
                 const float4* __restrict__ b4,
                 float4* __restrict__ outs4,
                 float4* __restrict__ outv4) {
    extern __shared__ float4 s_stash[];          // SMEM_F4 entries
    __shared__ float red[2][3][NWARPS];          // parity double buffer

    int t = threadIdx.x;
    int warp = t >> 5, lane = t & 31;
    int parity = 0;

    for (int seg = blockIdx.x; seg < NSEG; seg += gridDim.x) {
        int start = __ldg(&g_seg_start[seg]);
        int count = __ldg(&g_seg_start[seg + 1]) - start;
        if (count == 0) continue;

        long long sbase = (long long)start * 64;   // float4 index into s
        long long vbase = (long long)start * 96;   // float4 index into v
        int ns4 = count * 64;
        int nv4 = count * 96;
        int stash_n = (ns4 < SMEM_F4) ? ns4 : SMEM_F4;

        // ---- Pass 1: read s (stash) + v, accumulate ----
        float ss = 0.0f, ss2 = 0.0f, sv2 = 0.0f;
#pragma unroll 2
        for (int i = t; i < ns4; i += THREADS) {
            float4 a = s4[sbase + i];
            if (i < SMEM_F4) s_stash[i] = a;
            ss  += a.x + a.y + a.z + a.w;
            ss2 += a.x * a.x + a.y * a.y + a.z * a.z + a.w * a.w;
        }
#pragma unroll 4
        for (int i = t; i < nv4; i += THREADS) {
            float4 a = v4[vbase + i];
            sv2 += a.x * a.x + a.y * a.y + a.z * a.z + a.w * a.w;
        }

        warp_sum3(ss, ss2, sv2);
        if (lane == 0) {
            red[parity][0][warp] = ss;
            red[parity][1][warp] = ss2;
            red[parity][2][warp] = sv2;
        }
        __syncthreads();   // the ONLY barrier per segment

        float a0 = red[parity][0][lane];
        float a1 = red[parity][1][lane];
        float a2 = red[parity][2][lane];
        warp_sum3(a0, a1, a2);
        parity ^= 1;

        float cnt = (float)count;
        float denom_s = cnt * 256.0f;
        float m = a0 / denom_s;
        float var = fmaxf(a1 / denom_s - m * m, EPS);
        float ivr = 1.0f / var;
        float ivm = 1.0f / fmaxf(a2 / (cnt * 128.0f), EPS);

        // ---- Pass 2 (LIFO): v first (L2 hit), then s (smem stash) ----
#pragma unroll 4
        for (int i = t; i < nv4; i += THREADS) {
            long long g = vbase + i;
            float4 a = __ldcs(&v4[g]);
            float4 o;
            o.x = a.x * ivm;
            o.y = a.y * ivm;
            o.z = a.z * ivm;
            o.w = a.w * ivm;
            __stcs(&outv4[g], o);
        }
#pragma unroll 2
        for (int i = t; i < ns4; i += THREADS) {
            long long g = sbase + i;
            float4 a = (i < stash_n) ? s_stash[i] : __ldcs(&s4[g]);
            int cg = i & 63;                 // 64 float4 per node row
            float4 w = __ldg(&w4[cg]);
            float4 b = __ldg(&b4[cg]);
            float4 o;
            o.x = (a.x - m) * ivr * w.x + b.x;
            o.y = (a.y - m) * ivr * w.y + b.y;
            o.z = (a.z - m) * ivr * w.z + b.z;
            o.w = (a.w - m) * ivr * w.w + b.w;
            __stcs(&outs4[g], o);
        }
    }
}

extern "C" void kernel_launch(void* const* d_in, const int* in_sizes, int n_in,
                              void* d_out, int out_size) {
    const float* s      = (const float*)d_in[0];
    const float* v      = (const float*)d_in[1];
    const float* weight = (const float*)d_in[2];
    const float* bias   = (const float*)d_in[3];
    const int*   batch  = (const int*)d_in[4];

    int n = in_sizes[4];
    float* out_s = (float*)d_out;
    float* out_v = out_s + (size_t)n * 256;

    bounds_scan_kernel<<<(n + 1023) / 1024, 1024>>>(batch, n);

    const int SMEM_BYTES = SMEM_F4 * 16;   // 96KB -> 2 CTAs/SM + s stash
    cudaFuncSetAttribute(fused_seg_kernel,
                         cudaFuncAttributeMaxDynamicSharedMemorySize, SMEM_BYTES);

    fused_seg_kernel<<<GRID, THREADS, SMEM_BYTES>>>(
        (const float4*)s, (const float4*)v,
        (const float4*)weight, (const float4*)bias,
        (float4*)out_s, (float4*)out_v);
}

// round 10
// speedup vs baseline: 1.1381x; 1.0325x over previous
#include <cuda_runtime.h>

#define NSEG 2048
#define EPS 1e-6f
#define THREADS 1024
#define NWARPS (THREADS / 32)
#define SMEM_F4 6144   // 96KB float4 stash: covers ~98% of a segment's s-data
#define GRID 304       // persistent: 2 CTAs/SM x 152 SMs

__device__ int g_seg_start[NSEG + 1];
__device__ int g_next_seg;

// Linear boundary scan (coalesced, no dependent-load chains) + reset the
// work-stealing counter for this launch/replay.
__global__ void bounds_scan_kernel(const int* __restrict__ batch, int n) {
    int i = blockIdx.x * blockDim.x + threadIdx.x;
    if (i >= n) return;
    int b1 = batch[i];
    if (i == 0) {
        g_next_seg = 0;
        for (int g = 0; g <= b1; g++) g_seg_start[g] = 0;
    } else {
        int b0 = batch[i - 1];
        for (int g = b0 + 1; g <= b1; g++) g_seg_start[g] = i;
    }
    if (i == n - 1) {
        for (int g = b1 + 1; g <= NSEG; g++) g_seg_start[g] = n;
    }
}

__device__ __forceinline__ void warp_sum3(float& a, float& b, float& c) {
#pragma unroll
    for (int o = 16; o > 0; o >>= 1) {
        a += __shfl_xor_sync(0xFFFFFFFFu, a, o);
        b += __shfl_xor_sync(0xFFFFFFFFu, b, o);
        c += __shfl_xor_sync(0xFFFFFFFFu, c, o);
    }
}

// Persistent CTAs with DYNAMIC work stealing (global atomic counter).
// Still exactly ONE barrier per segment: thread 0 fetches the NEXT segment
// id right before the reduction barrier, so the fetch is covered by the
// barrier that publishes the partial sums. Per segment:
//   pass 1: read s (stash in 96KB smem) + v, accumulate 3 sums
//   barrier (publishes partials + next seg id)
//   every warp redundantly reduces; stats per-thread
//   pass 2: v from L2 (LIFO), s from private smem stash; streaming stores.
__global__ void __launch_bounds__(THREADS, 2)
fused_seg_kernel(const float4* __restrict__ s4,
                 const float4* __restrict__ v4,
                 const float4* __restrict__ w4,
                 const float4* __restrict__ b4,
                 float4* __restrict__ outs4,
                 float4* __restrict__ outv4) {
    extern __shared__ float4 s_stash[];          // SMEM_F4 entries
    __shared__ float red[2][3][NWARPS];          // parity double buffer
    __shared__ int sh_seg[2];

    int t = threadIdx.x;
    int warp = t >> 5, lane = t & 31;
    int parity = 0;

    // Fetch first segment (one extra barrier total, not per segment).
    if (t == 0) sh_seg[0] = atomicAdd(&g_next_seg, 1);
    __syncthreads();
    int seg = sh_seg[0];

    while (seg < NSEG) {
        int start = __ldg(&g_seg_start[seg]);
        int count = __ldg(&g_seg_start[seg + 1]) - start;

        long long sbase = (long long)start * 64;   // float4 index into s
        long long vbase = (long long)start * 96;   // float4 index into v
        int ns4 = count * 64;
        int nv4 = count * 96;
        int stash_n = (ns4 < SMEM_F4) ? ns4 : SMEM_F4;

        // ---- Pass 1: read s (stash) + v, accumulate ----
        float ss = 0.0f, ss2 = 0.0f, sv2 = 0.0f;
#pragma unroll 2
        for (int i = t; i < ns4; i += THREADS) {
            float4 a = s4[sbase + i];
            if (i < SMEM_F4) s_stash[i] = a;
            ss  += a.x + a.y + a.z + a.w;
            ss2 += a.x * a.x + a.y * a.y + a.z * a.z + a.w * a.w;
        }
#pragma unroll 6
        for (int i = t; i < nv4; i += THREADS) {
            float4 a = v4[vbase + i];
            sv2 += a.x * a.x + a.y * a.y + a.z * a.z + a.w * a.w;
        }

        warp_sum3(ss, ss2, sv2);
        if (t == 0) sh_seg[parity ^ 1] = atomicAdd(&g_next_seg, 1);
        if (lane == 0) {
            red[parity][0][warp] = ss;
            red[parity][1][warp] = ss2;
            red[parity][2][warp] = sv2;
        }
        __syncthreads();   // the ONLY barrier per segment

        if (count > 0) {
            // Redundant cross-warp reduce in every warp.
            float a0 = red[parity][0][lane];
            float a1 = red[parity][1][lane];
            float a2 = red[parity][2][lane];
            warp_sum3(a0, a1, a2);

            float cnt = (float)count;
            float denom_s = cnt * 256.0f;
            float m = a0 / denom_s;
            float var = fmaxf(a1 / denom_s - m * m, EPS);
            float ivr = 1.0f / var;
            float ivm = 1.0f / fmaxf(a2 / (cnt * 128.0f), EPS);

            // ---- Pass 2 (LIFO): v first (L2 hit), then s (smem stash) ----
#pragma unroll 6
            for (int i = t; i < nv4; i += THREADS) {
                long long g = vbase + i;
                float4 a = __ldcs(&v4[g]);
                float4 o;
                o.x = a.x * ivm;
                o.y = a.y * ivm;
                o.z = a.z * ivm;
                o.w = a.w * ivm;
                __stcs(&outv4[g], o);
            }
#pragma unroll 2
            for (int i = t; i < ns4; i += THREADS) {
                long long g = sbase + i;
                float4 a = (i < stash_n) ? s_stash[i] : __ldcs(&s4[g]);
                int cg = i & 63;                 // 64 float4 per node row
                float4 w = __ldg(&w4[cg]);
                float4 b = __ldg(&b4[cg]);
                float4 o;
                o.x = (a.x - m) * ivr * w.x + b.x;
                o.y = (a.y - m) * ivr * w.y + b.y;
                o.z = (a.z - m) * ivr * w.z + b.z;
                o.w = (a.w - m) * ivr * w.w + b.w;
                __stcs(&outs4[g], o);
            }
        }

        seg = sh_seg[parity ^ 1];
        parity ^= 1;
    }
}

extern "C" void kernel_launch(void* const* d_in, const int* in_sizes, int n_in,
                              void* d_out, int out_size) {
    const float* s      = (const float*)d_in[0];
    const float* v      = (const float*)d_in[1];
    const float* weight = (const float*)d_in[2];
    const float* bias   = (const float*)d_in[3];
    const int*   batch  = (const int*)d_in[4];

    int n = in_sizes[4];
    float* out_s = (float*)d_out;
    float* out_v = out_s + (size_t)n * 256;

    bounds_scan_kernel<<<(n + 1023) / 1024, 1024>>>(batch, n);

    const int SMEM_BYTES = SMEM_F4 * 16;   // 96KB -> 2 CTAs/SM + s stash
    cudaFuncSetAttribute(fused_seg_kernel,
                         cudaFuncAttributeMaxDynamicSharedMemorySize, SMEM_BYTES);

    fused_seg_kernel<<<GRID, THREADS, SMEM_BYTES>>>(
        (const float4*)s, (const float4*)v,
        (const float4*)weight, (const float4*)bias,
        (float4*)out_s, (float4*)out_v);
}